// round 15
// baseline (speedup 1.0000x reference)
#include <cuda_runtime.h>
#include <cuda_fp16.h>
#include <cstdint>

// CARAFE3D: x[2,32,32,32,32] -> out[2,16,64,64,64]
//   k_init: blocks 0..255: t = W_down@x + b_down, z = W_out@x ([n][c/4][loc][4]);
//           blocks 256..303: W_enc -> fp16 mma-fragment-major + tap tables
//   k_fuse: persistent, 2 CTA/SM. Per 64-voxel tile:
//             MMA phase (W streamed from L2, t-region in smem, fp16 mma.sync)
//             -> enc exchanged via smem -> softmax + reassembly + pixel shuffle.
//           No g_enc global round-trip.
typedef unsigned long long ull;
typedef unsigned int u32;
typedef unsigned short u16;

#define VOX 32768
#define GV_TOTAL 65536
#define NTILES 1024            // 64 voxels per tile

__device__ float g_t[2 * 8 * VOX];
__device__ __align__(16) float g_z[2 * 16 * VOX];        // [n][c/4][loc][4]
__device__ __align__(16) uint2 g_wfrag[12096];           // [chunk14][ntg27][lane32]
__device__ u16 g_tapoff[224];

#define REG_N 3352             // region floats (3264 data + zero tail)

__device__ __forceinline__ ull dup2(float a) {
    ull r; unsigned u = __float_as_uint(a);
    asm("mov.b64 %0, {%1, %1};" : "=l"(r) : "r"(u));
    return r;
}
__device__ __forceinline__ ull pack2(float a, float b) {
    ull r;
    asm("mov.b64 %0, {%1, %2};" : "=l"(r) : "r"(__float_as_uint(a)), "r"(__float_as_uint(b)));
    return r;
}
__device__ __forceinline__ ull ffma2(ull a, ull b, ull c) {
    ull d;
    asm("fma.rn.f32x2 %0, %1, %2, %3;" : "=l"(d) : "l"(a), "l"(b), "l"(c));
    return d;
}
#define MMA_F16(d, a, b0_, b1_) \
    asm volatile("mma.sync.aligned.m16n8k16.row.col.f32.f16.f16.f32 " \
        "{%0,%1,%2,%3}, {%4,%5,%6,%7}, {%8,%9}, {%0,%1,%2,%3};" \
        : "+f"((d)[0]), "+f"((d)[1]), "+f"((d)[2]), "+f"((d)[3]) \
        : "r"((a)[0]), "r"((a)[1]), "r"((a)[2]), "r"((a)[3]), "r"(b0_), "r"(b1_))

__device__ __forceinline__ unsigned short f16bits(float v) {
    __half h = __float2half_rn(v);
    return *(unsigned short*)&h;
}
__device__ __forceinline__ u32 h2pack(float a, float b) {
    __half2 h = __floats2half2_rn(a, b);     // low = a
    return *(u32*)&h;
}

// ---------------- k_init: down projections (blocks 0..255) + W prep (256..303) ----
__global__ __launch_bounds__(256) void k_init(
    const float* __restrict__ x,
    const float* __restrict__ wd, const float* __restrict__ bd,
    const float* __restrict__ wo,
    const float* __restrict__ w_enc)
{
    int tid = threadIdx.x;
    if (blockIdx.x >= 256) {
        int i = (blockIdx.x - 256) * 256 + tid;
        if (i < 12096) {
            int chunk = i / 864;
            int rem = i - chunk * 864;
            int ntg = rem >> 5;
            int lane = rem & 31;
            int g = lane >> 2, tc = lane & 3;
            int oc = ntg * 8 + g;
            int kb = chunk * 16;
            int ks[4] = { kb + 2 * tc, kb + 2 * tc + 1, kb + 8 + 2 * tc, kb + 9 + 2 * tc };
            unsigned short hh[4];
#pragma unroll
            for (int j = 0; j < 4; j++) {
                float v = (ks[j] < 216) ? w_enc[oc * 216 + ks[j]] : 0.f;
                hh[j] = f16bits(v);
            }
            uint2 q;
            q.x = (u32)hh[0] | ((u32)hh[1] << 16);
            q.y = (u32)hh[2] | ((u32)hh[3] << 16);
            g_wfrag[i] = q;
        }
        if (i < 224) {
            if (i < 216) {
                int ci = i / 27;
                int tap = i - ci * 27;
                int th = tap / 9;
                int tr = tap - th * 9;
                int tw = tr / 3;
                int td = tr - tw * 3;
                g_tapoff[i] = (u16)((((ci * 3 + th) * 4 + tw) * 34) + td);
            } else {
                g_tapoff[i] = (u16)3264;
            }
        }
        return;
    }

    __shared__ float swd[8 * 32];
    __shared__ float swo[16 * 32];
    if (tid < 256) swd[tid] = wd[tid];
    swo[tid] = wo[tid];
    swo[tid + 256] = wo[tid + 256];
    __syncthreads();

    int gv = blockIdx.x * 256 + tid;
    int n = gv >> 15;
    int loc = gv & (VOX - 1);
    const float* xb = x + n * (32 * VOX) + loc;

    float xv[32];
#pragma unroll
    for (int c = 0; c < 32; c++) xv[c] = xb[c * VOX];
#pragma unroll
    for (int m = 0; m < 8; m++) {
        float acc = bd[m];
#pragma unroll
        for (int c = 0; c < 32; c++) acc += swd[m * 32 + c] * xv[c];
        g_t[(n * 8 + m) * VOX + loc] = acc;
    }
    float za[16];
#pragma unroll
    for (int m = 0; m < 16; m++) {
        float acc = 0.f;
#pragma unroll
        for (int c = 0; c < 32; c++) acc += swo[m * 32 + c] * xv[c];
        za[m] = acc;
    }
#pragma unroll
    for (int cg = 0; cg < 4; cg++)
        *(float4*)(g_z + ((size_t)(n * 4 + cg) * VOX + loc) * 4) =
            make_float4(za[cg * 4], za[cg * 4 + 1], za[cg * 4 + 2], za[cg * 4 + 3]);
}

// ---------------- k_fuse: persistent fused enc GEMM + softmax + reassembly -------
// Smem (bytes): [0,448) taps; [448, +13408) t region; [13856, +56160) enc exchange.
#define TAP_OFF 0
#define REGION_OFF 448
#define ENC_OFF 13856
#define ENC_STRIDE 260
#define SMEM_FUSE 70016

__device__ __forceinline__ float region_val(int idx, int h, int w0, int base_t) {
    if (idx >= 3264) return 0.f;
    int ci = idx / 408;
    int r1 = idx - ci * 408;
    int hh = r1 / 136;
    int r2 = r1 - hh * 136;
    int ww = r2 / 34;
    int dd = r2 - ww * 34;
    int hs = h + hh - 1, ws = w0 + ww - 1, ds = dd - 1;
    if ((unsigned)hs < 32u && (unsigned)ws < 32u && (unsigned)ds < 32u)
        return g_t[base_t + ci * VOX + (hs << 10) + (ws << 5) + ds];
    return 0.f;
}

__global__ __launch_bounds__(256, 2) void k_fuse(const float* __restrict__ b_enc,
                                                 const float* __restrict__ b_out,
                                                 float* __restrict__ out)
{
    extern __shared__ __align__(16) char smem[];
    float* region = (float*)(smem + REGION_OFF);
    float* enc_s = (float*)(smem + ENC_OFF);
    const u16* s_tap = (const u16*)(smem + TAP_OFF);
    int tid = threadIdx.x;

    if (tid < 224) ((u16*)(smem + TAP_OFF))[tid] = g_tapoff[tid];

    int warp = tid >> 5, lane = tid & 31;
    int warp_m = warp & 3;
    int warp_n = warp >> 2;
    int g = lane >> 2, tc = lane & 3;
    int nts = warp_n ? 13 : 14;

    int vA = warp_m * 16 + g;
    int vB = vA + 8;
    int aoffA = (vA >> 5) * 34 + (vA & 31);
    int aoffB = (vB >> 5) * 34 + (vB & 31);

    // out-phase mapping: 4 threads per voxel
    int vloc = tid & 63;
    int tq = tid >> 6;
    int qh2 = tq & 1;            // rh half
    int cgh = tq >> 1;           // channel half (c 0..7 / 8..15)
    int wv = vloc >> 5, dv = vloc & 31;

    float bo[8];
#pragma unroll
    for (int c8 = 0; c8 < 8; c8++) bo[c8] = __ldg(b_out + cgh * 8 + c8);

    int tile = blockIdx.x;
    float rv[14];
    {
        int h = ((tile * 64) & (VOX - 1)) >> 10;
        int w0 = ((tile * 64) >> 5) & 31;
        int base_t = (tile >= 512) ? 8 * VOX : 0;
#pragma unroll
        for (int it = 0; it < 14; it++) {
            int idx = tid + it * 256;
            rv[it] = (idx < REG_N) ? region_val(idx, h, w0, base_t) : 0.f;
        }
    }

    for (; tile < NTILES; tile += gridDim.x) {
        int gv0 = tile * 64;
        int n = gv0 >> 15;
        int loc0 = gv0 & (VOX - 1);
        int h = loc0 >> 10;
        int w0 = (loc0 >> 5) & 31;

        __syncthreads();             // region + enc_s free (prev out done)
#pragma unroll
        for (int it = 0; it < 14; it++) {
            int idx = tid + it * 256;
            if (idx < REG_N) region[idx] = rv[it];
        }
        __syncthreads();             // region ready

        // prefetch next tile's region under the MMA mainloop
        int ntile = tile + gridDim.x;
        if (ntile < NTILES) {
            int nh = ((ntile * 64) & (VOX - 1)) >> 10;
            int nw0 = ((ntile * 64) >> 5) & 31;
            int nbase_t = (ntile >= 512) ? 8 * VOX : 0;
#pragma unroll
            for (int it = 0; it < 14; it++) {
                int idx = tid + it * 256;
                rv[it] = (idx < REG_N) ? region_val(idx, nh, nw0, nbase_t) : 0.f;
            }
        }

        // ---- MMA phase (W streamed from L2) ----
        float acc[14][4];
#pragma unroll
        for (int t = 0; t < 14; t++)
#pragma unroll
            for (int q = 0; q < 4; q++) acc[t][q] = 0.f;

#pragma unroll
        for (int chunk = 0; chunk < 14; chunk++) {
            const u16* tp = s_tap + chunk * 16;
            int t0 = tp[2 * tc], t1 = tp[2 * tc + 1];
            int t2k = tp[8 + 2 * tc], t3 = tp[9 + 2 * tc];
            u32 aa[4];
            aa[0] = h2pack(region[t0 + aoffA], region[t1 + aoffA]);
            aa[1] = h2pack(region[t0 + aoffB], region[t1 + aoffB]);
            aa[2] = h2pack(region[t2k + aoffA], region[t3 + aoffA]);
            aa[3] = h2pack(region[t2k + aoffB], region[t3 + aoffB]);

#pragma unroll
            for (int nt = 0; nt < 14; nt++) {
                if (nt >= nts) break;
                int ntg = warp_n * 14 + nt;
                uint2 wf = __ldg(&g_wfrag[(chunk * 27 + ntg) * 32 + lane]);
                MMA_F16(acc[nt], aa, wf.x, wf.y);
            }
        }

        // epilogue: acc + bias -> enc_s [grp][vox*4 + j]
#pragma unroll
        for (int nt = 0; nt < 14; nt++) {
            if (nt >= nts) break;
            int ntg = warp_n * 14 + nt;
            int oc = ntg * 8 + tc * 2;
            float bx = __ldg(b_enc + oc), by = __ldg(b_enc + oc + 1);
            int grp = ntg * 2 + (tc >> 1);
            int j = (tc & 1) * 2;
            int v0l = warp_m * 16 + g;
            float* ep = enc_s + grp * ENC_STRIDE + v0l * 4 + j;
            *(float2*)ep = make_float2(acc[nt][0] + bx, acc[nt][1] + by);
            *(float2*)(ep + 32) = make_float2(acc[nt][2] + bx, acc[nt][3] + by);
        }
        __syncthreads();             // enc_s ready

        // ---- out phase: softmax + reassembly + pixel shuffle ----
        const float* zb = g_z + (size_t)n * (16 * VOX);
        ull oacc[8][2];
#pragma unroll
        for (int c8 = 0; c8 < 8; c8++) { oacc[c8][0] = 0ull; oacc[c8][1] = 0ull; }
        float Z0 = 0.f, Z1 = 0.f, Z2 = 0.f, Z3 = 0.f;

#pragma unroll
        for (int k = 0; k < 27; k++) {
            const int thp = k / 9 - 1;
            const int twp = (k / 3) % 3 - 1;
            const int tdp = k % 3 - 1;
            int hh = h + thp, ww = w0 + wv + twp, dd = dv + tdp;
            bool ok = ((unsigned)hh < 32u) && ((unsigned)ww < 32u) && ((unsigned)dd < 32u);
            int zloc = (hh << 10) + (ww << 5) + dd;

            float4 e = *(const float4*)(enc_s + (k * 2 + qh2) * ENC_STRIDE + vloc * 4);
            float p0 = __expf(e.x), p1 = __expf(e.y), p2 = __expf(e.z), p3 = __expf(e.w);
            Z0 += p0; Z1 += p1; Z2 += p2; Z3 += p3;
            ull kr0 = pack2(p0, p1), kr1 = pack2(p2, p3);

            float4 zq0, zq1;
            if (ok) {
                zq0 = __ldg((const float4*)(zb + ((size_t)(cgh * 2) * VOX + zloc) * 4));
                zq1 = __ldg((const float4*)(zb + ((size_t)(cgh * 2 + 1) * VOX + zloc) * 4));
            } else {
                zq0 = zq1 = make_float4(0.f, 0.f, 0.f, 0.f);
            }
            float zsv[8] = { zq0.x, zq0.y, zq0.z, zq0.w, zq1.x, zq1.y, zq1.z, zq1.w };
#pragma unroll
            for (int c8 = 0; c8 < 8; c8++) {
                ull zz = dup2(zsv[c8]);
                oacc[c8][0] = ffma2(kr0, zz, oacc[c8][0]);
                oacc[c8][1] = ffma2(kr1, zz, oacc[c8][1]);
            }
        }

        ull iz0 = pack2(1.f / Z0, 1.f / Z1);
        ull iz1 = pack2(1.f / Z2, 1.f / Z3);

        int d = dv, w = w0 + wv;
#pragma unroll
        for (int c8 = 0; c8 < 8; c8++) {
            int c = cgh * 8 + c8;
            ull b2 = dup2(bo[c8]);
            int cbase = (n * 16 + c) * 64;
#pragma unroll
            for (int jq = 0; jq < 2; jq++) {
                ull res = ffma2(jq ? oacc[c8][1] : oacc[c8][0], jq ? iz1 : iz0, b2);
                int addr = (((cbase + h * 2 + qh2) * 64) + (w * 2 + jq)) * 64 + d * 2;
                *(ull*)(out + addr) = res;
            }
        }
    }
}

extern "C" void kernel_launch(void* const* d_in, const int* in_sizes, int n_in,
                              void* d_out, int out_size) {
    const float* x      = (const float*)d_in[0];
    const float* w_down = (const float*)d_in[1];
    const float* b_down = (const float*)d_in[2];
    const float* w_enc  = (const float*)d_in[3];
    const float* b_enc  = (const float*)d_in[4];
    const float* w_out  = (const float*)d_in[5];
    const float* b_out  = (const float*)d_in[6];
    float* out = (float*)d_out;

    cudaFuncSetAttribute(k_fuse, cudaFuncAttributeMaxDynamicSharedMemorySize, SMEM_FUSE);

    k_init<<<304, 256>>>(x, w_down, b_down, w_out, w_enc);
    k_fuse<<<296, 256, SMEM_FUSE>>>(b_enc, b_out, out);
}